// round 1
// baseline (speedup 1.0000x reference)
#include <cuda_runtime.h>
#include <math.h>

#define B    8
#define LQ   512
#define LK   1024
#define DIN  768
#define HID  1024
#define MID  4096
#define NH   16
#define DH   64

// ---------------- scratch (device globals; no allocation allowed) ----------
__device__ float g_qp[B*LQ*DIN];
__device__ float g_qh[B*LQ*HID];
__device__ float g_q0p[B*LQ*HID];
__device__ float g_kh[B*LK*HID];
__device__ float g_v1[B*LK*HID];
__device__ float g_v0[B*LK*HID];
__device__ float g_scores[(size_t)B*NH*LQ*LK];   // 268 MB
__device__ float g_atted_raw[B*LQ*HID];
__device__ float g_s[B*LQ*HID];
__device__ float g_atted[B*LQ*HID];
__device__ float g_ff1[B*LQ*MID];
__device__ float g_ff2[B*LQ*HID];
__device__ float g_xraw[B*HID];

// ---------------- positional encoding add ---------------------------------
// pe[l, 2i] = sin(l*div_i), pe[l, 2i+1] = cos(l*div_i), div_i = exp(-2i*ln(1e4)/768)
__global__ void addpe_kernel(const float* __restrict__ in, float* __restrict__ out,
                             int total, int L)
{
    int idx = blockIdx.x * 256 + threadIdx.x;
    if (idx >= total) return;
    int d = idx % DIN;
    int l = (idx / DIN) % L;
    int i2 = d & ~1;                 // 2*(d/2)
    const float c = 9.2103403719761836f / (float)DIN;   // ln(10000)/768
    float freq = expf(-(float)i2 * c);
    float ang  = (float)l * freq;
    float pe   = (d & 1) ? cosf(ang) : sinf(ang);
    out[idx] = in[idx] + pe;
}

// ---------------- generic SGEMM: C[M,N] = A[M,K] @ W[K,N] + bias, opt relu -
// 64x64 tile, K-tile 16, 256 threads, 4x4 per thread. All dims multiples of 64/16.
__global__ void sgemm_bias(const float* __restrict__ A, const float* __restrict__ W,
                           const float* __restrict__ bias, float* __restrict__ C,
                           int M, int N, int K, int relu)
{
    __shared__ float As[16][68];   // [kk][m], padded
    __shared__ float Bs[16][68];   // [kk][n], padded
    int tid = threadIdx.x;
    int tx = tid & 15, ty = tid >> 4;
    int row0 = blockIdx.y * 64, col0 = blockIdx.x * 64;
    float acc[4][4] = {};

    for (int k0 = 0; k0 < K; k0 += 16) {
        #pragma unroll
        for (int i = 0; i < 4; i++) {
            int l = tid + i * 256;           // 0..1023
            int m = l >> 4, kk = l & 15;
            As[kk][m] = A[(size_t)(row0 + m) * K + k0 + kk];
        }
        #pragma unroll
        for (int i = 0; i < 4; i++) {
            int l = tid + i * 256;
            int kk = l >> 6, n = l & 63;
            Bs[kk][n] = W[(size_t)(k0 + kk) * N + col0 + n];
        }
        __syncthreads();
        #pragma unroll
        for (int kk = 0; kk < 16; kk++) {
            float a[4], b[4];
            #pragma unroll
            for (int i = 0; i < 4; i++) a[i] = As[kk][ty * 4 + i];
            #pragma unroll
            for (int j = 0; j < 4; j++) b[j] = Bs[kk][tx * 4 + j];
            #pragma unroll
            for (int i = 0; i < 4; i++)
                #pragma unroll
                for (int j = 0; j < 4; j++)
                    acc[i][j] = fmaf(a[i], b[j], acc[i][j]);
        }
        __syncthreads();
    }
    #pragma unroll
    for (int i = 0; i < 4; i++) {
        int r = row0 + ty * 4 + i;
        #pragma unroll
        for (int j = 0; j < 4; j++) {
            int cidx = col0 + tx * 4 + j;
            float v = acc[i][j] + bias[cidx];
            if (relu) v = fmaxf(v, 0.0f);
            C[(size_t)r * N + cidx] = v;
        }
    }
}

// ---------------- scores: per (b,h) NT gemm [512,64]x[1024,64]^T ----------
// scores[b,h,q,k] = (1/8) * sum_d qh[b,q,h*64+d] * kh[b,k,h*64+d]
__global__ void gemm_scores(const float* __restrict__ qh, const float* __restrict__ kh,
                            float* __restrict__ S)
{
    __shared__ float Qs[64][65];   // [q][d]
    __shared__ float Ks[64][65];   // [k][d]
    int bh = blockIdx.z, b = bh >> 4, h = bh & 15;
    int q0 = blockIdx.y * 64, k0 = blockIdx.x * 64;
    const float* Qb = qh + (size_t)b * LQ * HID + h * 64;
    const float* Kb = kh + (size_t)b * LK * HID + h * 64;
    int tid = threadIdx.x, tx = tid & 15, ty = tid >> 4;

    #pragma unroll
    for (int i = 0; i < 16; i++) {
        int l = tid + i * 256;
        int r = l >> 6, d = l & 63;
        Qs[r][d] = Qb[(size_t)(q0 + r) * HID + d];
        Ks[r][d] = Kb[(size_t)(k0 + r) * HID + d];
    }
    __syncthreads();

    float acc[4][4] = {};
    #pragma unroll 8
    for (int d = 0; d < 64; d++) {
        float a[4], bb[4];
        #pragma unroll
        for (int i = 0; i < 4; i++) a[i]  = Qs[ty * 4 + i][d];
        #pragma unroll
        for (int j = 0; j < 4; j++) bb[j] = Ks[tx * 4 + j][d];
        #pragma unroll
        for (int i = 0; i < 4; i++)
            #pragma unroll
            for (int j = 0; j < 4; j++)
                acc[i][j] = fmaf(a[i], bb[j], acc[i][j]);
    }
    float* Sb = S + (size_t)bh * LQ * LK;
    #pragma unroll
    for (int i = 0; i < 4; i++)
        #pragma unroll
        for (int j = 0; j < 4; j++)
            Sb[(size_t)(q0 + ty * 4 + i) * LK + k0 + tx * 4 + j] = acc[i][j] * 0.125f;
}

// ---------------- att_out: relu(scores).sum over heads / 16 ---------------
__global__ void attout_kernel(const float* __restrict__ S, float* __restrict__ O)
{
    int bq = blockIdx.x;           // b*LQ + q
    int b = bq >> 9, q = bq & 511;
    int tid = threadIdx.x;
    #pragma unroll
    for (int i = 0; i < 4; i++) {
        int kc = tid + i * 256;
        float s = 0.0f;
        #pragma unroll
        for (int h = 0; h < NH; h++) {
            float x = S[(((size_t)(b * NH + h) * LQ) + q) * LK + kc];
            s += fmaxf(x, 0.0f);
        }
        O[(size_t)bq * LK + kc] = s * (1.0f / 16.0f);
    }
}

// ---------------- in-place row softmax (row = 1024) -----------------------
__global__ void softmax1024(float* __restrict__ P)
{
    __shared__ float red[256];
    size_t base = (size_t)blockIdx.x * 1024;
    int tid = threadIdx.x;
    float v[4];
    #pragma unroll
    for (int i = 0; i < 4; i++) v[i] = P[base + tid + i * 256];
    float m = fmaxf(fmaxf(v[0], v[1]), fmaxf(v[2], v[3]));
    red[tid] = m; __syncthreads();
    for (int o = 128; o > 0; o >>= 1) { if (tid < o) red[tid] = fmaxf(red[tid], red[tid + o]); __syncthreads(); }
    m = red[0]; __syncthreads();
    float s = 0.0f;
    #pragma unroll
    for (int i = 0; i < 4; i++) { v[i] = expf(v[i] - m); s += v[i]; }
    red[tid] = s; __syncthreads();
    for (int o = 128; o > 0; o >>= 1) { if (tid < o) red[tid] += red[tid + o]; __syncthreads(); }
    float inv = 1.0f / red[0];
    #pragma unroll
    for (int i = 0; i < 4; i++) P[base + tid + i * 256] = v[i] * inv;
}

// ---------------- att @ Vhead: out[b,q,h*64+d] = sum_k att[bh,q,k]*v[b,k,h*64+d]
__global__ void gemm_attv(const float* __restrict__ att, const float* __restrict__ V,
                          float* __restrict__ out)
{
    __shared__ float As[16][68];   // [kk][q]
    __shared__ float Bs[16][68];   // [kk][d]
    int bh = blockIdx.z, b = bh >> 4, h = bh & 15;
    int q0 = blockIdx.y * 64;
    const float* Ab = att + (size_t)bh * LQ * LK;
    const float* Bb = V + (size_t)b * LK * HID + h * 64;
    float* Cb = out + (size_t)b * LQ * HID + h * 64;
    int tid = threadIdx.x, tx = tid & 15, ty = tid >> 4;
    float acc[4][4] = {};

    for (int k0 = 0; k0 < LK; k0 += 16) {
        #pragma unroll
        for (int i = 0; i < 4; i++) {
            int l = tid + i * 256;
            int m = l >> 4, kk = l & 15;
            As[kk][m] = Ab[(size_t)(q0 + m) * LK + k0 + kk];
        }
        {
            int l = tid;                        // 16x64 = 1024 elems, 4 per thread
            #pragma unroll
            for (int i = 0; i < 4; i++) {
                int ll = l + i * 256;
                int kk = ll >> 6, d = ll & 63;
                Bs[kk][d] = Bb[(size_t)(k0 + kk) * HID + d];
            }
        }
        __syncthreads();
        #pragma unroll
        for (int kk = 0; kk < 16; kk++) {
            float a[4], bb[4];
            #pragma unroll
            for (int i = 0; i < 4; i++) a[i]  = As[kk][ty * 4 + i];
            #pragma unroll
            for (int j = 0; j < 4; j++) bb[j] = Bs[kk][tx * 4 + j];
            #pragma unroll
            for (int i = 0; i < 4; i++)
                #pragma unroll
                for (int j = 0; j < 4; j++)
                    acc[i][j] = fmaf(a[i], bb[j], acc[i][j]);
        }
        __syncthreads();
    }
    #pragma unroll
    for (int i = 0; i < 4; i++)
        #pragma unroll
        for (int j = 0; j < 4; j++)
            Cb[(size_t)(q0 + ty * 4 + i) * HID + tx * 4 + j] = acc[i][j];
}

// ---------------- bilinear column-dot: xraw[b,c] = sum_v q0p[b,v,c]*s[b,v,c]
__global__ void xreduce_kernel(const float* __restrict__ q0p, const float* __restrict__ s,
                               float* __restrict__ xraw)
{
    int b = blockIdx.y;
    int c = blockIdx.x * 256 + threadIdx.x;
    const float* A  = q0p + (size_t)b * LQ * HID;
    const float* Bp = s   + (size_t)b * LQ * HID;
    float acc = 0.0f;
    for (int v = 0; v < LQ; v++)
        acc = fmaf(A[(size_t)v * HID + c], Bp[(size_t)v * HID + c], acc);
    xraw[b * HID + c] = acc;
}

// ---------------- torch LN: a*(x-mean)/(sqrt(unbiased var)+eps)+b, n=1024 --
__global__ void ln1024(const float* __restrict__ X, const float* __restrict__ R,
                       const float* __restrict__ ga, const float* __restrict__ be,
                       float* __restrict__ Y)
{
    __shared__ float red[256];
    int row = blockIdx.x, tid = threadIdx.x;
    size_t base = (size_t)row * 1024;
    float v[4];
    #pragma unroll
    for (int i = 0; i < 4; i++) {
        int c = tid + i * 256;
        v[i] = X[base + c];
        if (R) v[i] += R[base + c];
    }
    float s = v[0] + v[1] + v[2] + v[3];
    red[tid] = s; __syncthreads();
    for (int o = 128; o > 0; o >>= 1) { if (tid < o) red[tid] += red[tid + o]; __syncthreads(); }
    float mean = red[0] * (1.0f / 1024.0f);
    __syncthreads();
    float ss = 0.0f;
    #pragma unroll
    for (int i = 0; i < 4; i++) { float d = v[i] - mean; ss = fmaf(d, d, ss); }
    red[tid] = ss; __syncthreads();
    for (int o = 128; o > 0; o >>= 1) { if (tid < o) red[tid] += red[tid + o]; __syncthreads(); }
    float var = red[0] * (1.0f / 1023.0f);      // unbiased (torch default)
    float inv = 1.0f / (sqrtf(var) + 1e-6f);    // (std + eps), NOT sqrt(var+eps)
    #pragma unroll
    for (int i = 0; i < 4; i++) {
        int c = tid + i * 256;
        Y[base + c] = ga[c] * (v[i] - mean) * inv + be[c];
    }
}

// ---------------- launch ---------------------------------------------------
extern "C" void kernel_launch(void* const* d_in, const int* in_sizes, int n_in,
                              void* d_out, int out_size)
{
    const float* q    = (const float*)d_in[0];
    const float* k    = (const float*)d_in[1];
    const float* Wq   = (const float*)d_in[2];
    const float* bq   = (const float*)d_in[3];
    const float* Wk   = (const float*)d_in[4];
    const float* bk   = (const float*)d_in[5];
    const float* Wv   = (const float*)d_in[6];
    const float* bv   = (const float*)d_in[7];
    const float* Wv0  = (const float*)d_in[8];
    const float* bv0  = (const float*)d_in[9];
    const float* Wq0  = (const float*)d_in[10];
    const float* bq0  = (const float*)d_in[11];
    const float* nq_a = (const float*)d_in[12];
    const float* nq_b = (const float*)d_in[13];
    const float* nx_a = (const float*)d_in[14];
    const float* nx_b = (const float*)d_in[15];
    const float* W1   = (const float*)d_in[16];
    const float* b1   = (const float*)d_in[17];
    const float* W2   = (const float*)d_in[18];
    const float* b2   = (const float*)d_in[19];
    const float* ns_a = (const float*)d_in[20];
    const float* ns_b = (const float*)d_in[21];

    float* out = (float*)d_out;
    // output packing: x[8,1024], qq[8,512,1024], kp[8,1024,768], att[8,512,1024]
    float* out_x   = out;
    float* out_qq  = out + (size_t)B * HID;
    float* out_kp  = out_qq + (size_t)B * LQ * HID;
    float* out_att = out_kp + (size_t)B * LK * DIN;

    float *p_qp, *p_qh, *p_q0p, *p_kh, *p_v1, *p_v0, *p_sc, *p_ar, *p_s, *p_at, *p_f1, *p_f2, *p_xr;
    cudaGetSymbolAddress((void**)&p_qp,  g_qp);
    cudaGetSymbolAddress((void**)&p_qh,  g_qh);
    cudaGetSymbolAddress((void**)&p_q0p, g_q0p);
    cudaGetSymbolAddress((void**)&p_kh,  g_kh);
    cudaGetSymbolAddress((void**)&p_v1,  g_v1);
    cudaGetSymbolAddress((void**)&p_v0,  g_v0);
    cudaGetSymbolAddress((void**)&p_sc,  g_scores);
    cudaGetSymbolAddress((void**)&p_ar,  g_atted_raw);
    cudaGetSymbolAddress((void**)&p_s,   g_s);
    cudaGetSymbolAddress((void**)&p_at,  g_atted);
    cudaGetSymbolAddress((void**)&p_f1,  g_ff1);
    cudaGetSymbolAddress((void**)&p_f2,  g_ff2);
    cudaGetSymbolAddress((void**)&p_xr,  g_xraw);

    // 1) positional encodings: qp (scratch), kp (output, also reused as input)
    {
        int tq = B * LQ * DIN, tk = B * LK * DIN;
        addpe_kernel<<<(tq + 255) / 256, 256>>>(q, p_qp, tq, LQ);
        addpe_kernel<<<(tk + 255) / 256, 256>>>(k, out_kp, tk, LK);
    }

    // 2) projections
    sgemm_bias<<<dim3(HID / 64, B * LQ / 64), 256>>>(p_qp,  Wq,  bq,  p_qh,  B * LQ, HID, DIN, 0);
    sgemm_bias<<<dim3(HID / 64, B * LQ / 64), 256>>>(q,     Wq0, bq0, p_q0p, B * LQ, HID, DIN, 0);
    sgemm_bias<<<dim3(HID / 64, B * LK / 64), 256>>>(out_kp, Wk,  bk,  p_kh,  B * LK, HID, DIN, 0);
    sgemm_bias<<<dim3(HID / 64, B * LK / 64), 256>>>(out_kp, Wv,  bv,  p_v1,  B * LK, HID, DIN, 0);
    sgemm_bias<<<dim3(HID / 64, B * LK / 64), 256>>>(out_kp, Wv0, bv0, p_v0,  B * LK, HID, DIN, 0);

    // 3) scores (scaled), att_out from pre-softmax scores, softmax in place
    gemm_scores<<<dim3(LK / 64, LQ / 64, B * NH), 256>>>(p_qh, p_kh, p_sc);
    attout_kernel<<<B * LQ, 256>>>(p_sc, out_att);
    softmax1024<<<B * NH * LQ, 256>>>(p_sc);

    // 4) att @ v1 -> atted_raw ; att @ v0 -> s
    gemm_attv<<<dim3(1, LQ / 64, B * NH), 256>>>(p_sc, p_v1, p_ar);
    gemm_attv<<<dim3(1, LQ / 64, B * NH), 256>>>(p_sc, p_v0, p_s);

    // 5) atted = LN(q0p + atted_raw)
    ln1024<<<B * LQ, 256>>>(p_ar, p_q0p, nq_a, nq_b, p_at);

    // 6) bilinear: xraw[b,c] = sum_v q0p*s ; x = LN(xraw)
    xreduce_kernel<<<dim3(HID / 256, B), 256>>>(p_q0p, p_s, p_xr);
    ln1024<<<B, 256>>>(p_xr, (const float*)nullptr, nx_a, nx_b, out_x);

    // 7) FFN + residual LN -> qq
    sgemm_bias<<<dim3(MID / 64, B * LQ / 64), 256>>>(p_at, W1, b1, p_f1, B * LQ, MID, HID, 1);
    sgemm_bias<<<dim3(HID / 64, B * LQ / 64), 256>>>(p_f1, W2, b2, p_f2, B * LQ, HID, MID, 0);
    ln1024<<<B * LQ, 256>>>(p_f2, p_at, ns_a, ns_b, out_qq);
}

// round 3
// speedup vs baseline: 1.9698x; 1.9698x over previous
#include <cuda_runtime.h>
#include <cuda_bf16.h>
#include <math.h>
#include <stdint.h>

#define B    8
#define LQ   512
#define LK   1024
#define DIN  768
#define HID  1024
#define MID  4096
#define NH   16
#define DH   64

// ---------------- fp32 scratch ---------------------------------------------
__device__ float g_qh[B*LQ*HID];
__device__ float g_q0p[B*LQ*HID];
__device__ float g_kh[B*LK*HID];
__device__ float g_v1[B*LK*HID];
__device__ float g_v0[B*LK*HID];
__device__ float g_scores[(size_t)B*NH*LQ*LK];   // 268 MB
__device__ float g_atted_raw[B*LQ*HID];
__device__ float g_s[B*LQ*HID];
__device__ float g_atted[B*LQ*HID];
__device__ float g_ff2[B*LQ*HID];
__device__ float g_xraw[B*HID];

// ---------------- bf16 split scratch (hi/lo) -------------------------------
__device__ __nv_bfloat16 g_qp_h[B*LQ*DIN],  g_qp_l[B*LQ*DIN];
__device__ __nv_bfloat16 g_q_h [B*LQ*DIN],  g_q_l [B*LQ*DIN];
__device__ __nv_bfloat16 g_kp_h[B*LK*DIN],  g_kp_l[B*LK*DIN];
__device__ __nv_bfloat16 g_at_h[B*LQ*HID],  g_at_l[B*LQ*HID];
__device__ __nv_bfloat16 g_f1_h[B*LQ*MID],  g_f1_l[B*LQ*MID];
__device__ __nv_bfloat16 g_WqT_h [HID*DIN], g_WqT_l [HID*DIN];
__device__ __nv_bfloat16 g_WkT_h [HID*DIN], g_WkT_l [HID*DIN];
__device__ __nv_bfloat16 g_WvT_h [HID*DIN], g_WvT_l [HID*DIN];
__device__ __nv_bfloat16 g_Wv0T_h[HID*DIN], g_Wv0T_l[HID*DIN];
__device__ __nv_bfloat16 g_Wq0T_h[HID*DIN], g_Wq0T_l[HID*DIN];
__device__ __nv_bfloat16 g_W1T_h [MID*HID], g_W1T_l [MID*HID];
__device__ __nv_bfloat16 g_W2T_h [HID*MID], g_W2T_l [HID*MID];

// ======================= small PTX helpers =================================
__device__ __forceinline__ uint32_t smem_u32(const void* p) {
    uint32_t a;
    asm("{ .reg .u64 t; cvta.to.shared.u64 t, %1; cvt.u32.u64 %0, t; }" : "=r"(a) : "l"(p));
    return a;
}
__device__ __forceinline__ void cp_async16(uint32_t dst, const void* src) {
    asm volatile("cp.async.cg.shared.global [%0], [%1], 16;" :: "r"(dst), "l"(src));
}
__device__ __forceinline__ void ldsm4(uint32_t* r, uint32_t addr) {
    asm volatile("ldmatrix.sync.aligned.m8n8.x4.shared.b16 {%0,%1,%2,%3}, [%4];"
                 : "=r"(r[0]), "=r"(r[1]), "=r"(r[2]), "=r"(r[3]) : "r"(addr));
}
__device__ __forceinline__ void mma16816(float* d, const uint32_t* a, uint32_t b0, uint32_t b1) {
    asm volatile("mma.sync.aligned.m16n8k16.row.col.f32.bf16.bf16.f32 "
                 "{%0,%1,%2,%3}, {%4,%5,%6,%7}, {%8,%9}, {%0,%1,%2,%3};"
                 : "+f"(d[0]), "+f"(d[1]), "+f"(d[2]), "+f"(d[3])
                 : "r"(a[0]), "r"(a[1]), "r"(a[2]), "r"(a[3]), "r"(b0), "r"(b1));
}

// ======================= bf16x3 HMMA GEMM ==================================
// C[M,N] = A[M,K] @ B[N,K]^T + bias, optional relu.
// A,B split into bf16 hi/lo. C = Ah*Bh + Ah*Bl + Al*Bh (fp32 accum).
// Block tile 128x128, BK=32, 256 threads (2m x 4n warps, 64x32 warp tile).
// Smem per stage: Ah(8K) Al(8K) Bh(8K) Bl(8K) = 32K; 2 stages = 64K.
#define MM_SMEM 65536

__device__ __forceinline__ uint32_t sw_off(int r, int c) {
    // row r (0-127), 16B chunk c (0-3) within 64B row; XOR swizzle
    return (uint32_t)(r * 64 + ((c ^ ((r >> 1) & 3)) << 4));
}

__global__ void __launch_bounds__(256, 1)
mm_bf16x3(const __nv_bfloat16* __restrict__ Ah_g, const __nv_bfloat16* __restrict__ Al_g,
          const __nv_bfloat16* __restrict__ Bh_g, const __nv_bfloat16* __restrict__ Bl_g,
          const float* __restrict__ bias, float* __restrict__ C,
          __nv_bfloat16* __restrict__ Ch, __nv_bfloat16* __restrict__ Cl,
          int M, int N, int K, int relu)
{
    extern __shared__ char smem[];
    const uint32_t sb = smem_u32(smem);
    const int tid = threadIdx.x, lane = tid & 31, warp = tid >> 5;
    const int wm = warp >> 2, wn = warp & 3;          // 2 x 4 warps
    const int row0 = blockIdx.y * 128, col0 = blockIdx.x * 128;

    float acc[4][4][4];
    #pragma unroll
    for (int i = 0; i < 4; i++)
        #pragma unroll
        for (int j = 0; j < 4; j++)
            #pragma unroll
            for (int e = 0; e < 4; e++) acc[i][j][e] = 0.0f;

    // ---- stage loader: 4 sub-tiles x 128 rows x 64B, 8 cp.async per thread
    auto load_stage = [&](int s, int k0) {
        uint32_t base = sb + s * 32768;
        #pragma unroll
        for (int i = 0; i < 2; i++) {
            int linear = tid + i * 256;               // 0..511
            int r = linear >> 2, c = linear & 3;
            uint32_t off = sw_off(r, c);
            const __nv_bfloat16* sA = Ah_g + (size_t)(row0 + r) * K + k0 + c * 8;
            const __nv_bfloat16* sAl = Al_g + (size_t)(row0 + r) * K + k0 + c * 8;
            const __nv_bfloat16* sB = Bh_g + (size_t)(col0 + r) * K + k0 + c * 8;
            const __nv_bfloat16* sBl = Bl_g + (size_t)(col0 + r) * K + k0 + c * 8;
            cp_async16(base +         off, sA);
            cp_async16(base +  8192 + off, sAl);
            cp_async16(base + 16384 + off, sB);
            cp_async16(base + 24576 + off, sBl);
        }
        asm volatile("cp.async.commit_group;" ::: "memory");
    };

    const int T = K / 32;
    load_stage(0, 0);

    for (int t = 0; t < T; t++) {
        if (t + 1 < T) {
            load_stage((t + 1) & 1, (t + 1) * 32);
            asm volatile("cp.async.wait_group 1;" ::: "memory");
        } else {
            asm volatile("cp.async.wait_group 0;" ::: "memory");
        }
        __syncthreads();

        uint32_t st = sb + (t & 1) * 32768;
        uint32_t aH = st, aL = st + 8192, bH = st + 16384, bL = st + 24576;

        #pragma unroll
        for (int ks = 0; ks < 2; ks++) {
            int cb = ks * 2;
            uint32_t a_h[4][4], a_l[4][4];
            {
                int r = wm * 64 + (lane & 15);
                int c = cb + (lane >> 4);
                #pragma unroll
                for (int mi = 0; mi < 4; mi++) {
                    uint32_t off = sw_off(r + mi * 16, c);
                    ldsm4(a_h[mi], aH + off);
                    ldsm4(a_l[mi], aL + off);
                }
            }
            uint32_t b_h[2][4], b_l[2][4];
            {
                int nr = wn * 32 + (lane & 7) + ((lane >> 4) & 1) * 8;
                int c = cb + ((lane >> 3) & 1);
                #pragma unroll
                for (int p = 0; p < 2; p++) {
                    uint32_t off = sw_off(nr + p * 16, c);
                    ldsm4(b_h[p], bH + off);
                    ldsm4(b_l[p], bL + off);
                }
            }
            #pragma unroll
            for (int mi = 0; mi < 4; mi++)
                #pragma unroll
                for (int nj = 0; nj < 4; nj++) {
                    const uint32_t* fh = &b_h[nj >> 1][(nj & 1) * 2];
                    const uint32_t* fl = &b_l[nj >> 1][(nj & 1) * 2];
                    mma16816(acc[mi][nj], a_h[mi], fh[0], fh[1]);
                    mma16816(acc[mi][nj], a_h[mi], fl[0], fl[1]);
                    mma16816(acc[mi][nj], a_l[mi], fh[0], fh[1]);
                }
        }
        __syncthreads();
    }

    // ---- epilogue
    #pragma unroll
    for (int mi = 0; mi < 4; mi++) {
        #pragma unroll
        for (int nj = 0; nj < 4; nj++) {
            int r_lo = row0 + wm * 64 + mi * 16 + (lane >> 2);
            int col  = col0 + wn * 32 + nj * 8 + ((lane & 3) << 1);
            float b0 = bias[col], b1 = bias[col + 1];
            #pragma unroll
            for (int half = 0; half < 2; half++) {
                int r = r_lo + half * 8;
                float v0 = acc[mi][nj][half * 2 + 0] + b0;
                float v1 = acc[mi][nj][half * 2 + 1] + b1;
                if (relu) { v0 = fmaxf(v0, 0.f); v1 = fmaxf(v1, 0.f); }
                if (C) {
                    C[(size_t)r * N + col]     = v0;
                    C[(size_t)r * N + col + 1] = v1;
                }
                if (Ch) {
                    __nv_bfloat16 h0 = __float2bfloat16(v0);
                    __nv_bfloat16 h1 = __float2bfloat16(v1);
                    Ch[(size_t)r * N + col]     = h0;
                    Ch[(size_t)r * N + col + 1] = h1;
                    Cl[(size_t)r * N + col]     = __float2bfloat16(v0 - __bfloat162float(h0));
                    Cl[(size_t)r * N + col + 1] = __float2bfloat16(v1 - __bfloat162float(h1));
                }
            }
        }
    }
}

// ======================= elementwise / transpose ===========================
__global__ void addpe_split(const float* __restrict__ in, float* __restrict__ outf,
                            __nv_bfloat16* __restrict__ oh, __nv_bfloat16* __restrict__ ol,
                            int total, int L)
{
    int idx = blockIdx.x * 256 + threadIdx.x;
    if (idx >= total) return;
    int d = idx % DIN;
    int l = (idx / DIN) % L;
    int i2 = d & ~1;
    const float c = 9.2103403719761836f / (float)DIN;
    float ang = (float)l * expf(-(float)i2 * c);
    float pe = (d & 1) ? cosf(ang) : sinf(ang);
    float v = in[idx] + pe;
    if (outf) outf[idx] = v;
    __nv_bfloat16 h = __float2bfloat16(v);
    oh[idx] = h;
    ol[idx] = __float2bfloat16(v - __bfloat162float(h));
}

__global__ void split_kernel(const float* __restrict__ in,
                             __nv_bfloat16* __restrict__ oh, __nv_bfloat16* __restrict__ ol, int n)
{
    int idx = blockIdx.x * 256 + threadIdx.x;
    if (idx >= n) return;
    float v = in[idx];
    __nv_bfloat16 h = __float2bfloat16(v);
    oh[idx] = h;
    ol[idx] = __float2bfloat16(v - __bfloat162float(h));
}

// W[K,N] -> Th/Tl[N,K] bf16
__global__ void transpose_split(const float* __restrict__ W,
                                __nv_bfloat16* __restrict__ Th, __nv_bfloat16* __restrict__ Tl,
                                int K, int N)
{
    __shared__ float t[32][33];
    int n0 = blockIdx.x * 32, k0 = blockIdx.y * 32;
    int tx = threadIdx.x, ty = threadIdx.y;
    #pragma unroll
    for (int j = 0; j < 4; j++)
        t[ty + j*8][tx] = W[(size_t)(k0 + ty + j*8) * N + n0 + tx];
    __syncthreads();
    #pragma unroll
    for (int j = 0; j < 4; j++) {
        int n = n0 + ty + j*8, kk = k0 + tx;
        float v = t[tx][ty + j*8];
        __nv_bfloat16 h = __float2bfloat16(v);
        Th[(size_t)n * K + kk] = h;
        Tl[(size_t)n * K + kk] = __float2bfloat16(v - __bfloat162float(h));
    }
}

// ======================= SIMT attention kernels (R1, passing) ==============
__global__ void gemm_scores(const float* __restrict__ qh, const float* __restrict__ kh,
                            float* __restrict__ S)
{
    __shared__ float Qs[64][65];
    __shared__ float Ks[64][65];
    int bh = blockIdx.z, b = bh >> 4, h = bh & 15;
    int q0 = blockIdx.y * 64, k0 = blockIdx.x * 64;
    const float* Qb = qh + (size_t)b * LQ * HID + h * 64;
    const float* Kb = kh + (size_t)b * LK * HID + h * 64;
    int tid = threadIdx.x, tx = tid & 15, ty = tid >> 4;
    #pragma unroll
    for (int i = 0; i < 16; i++) {
        int l = tid + i * 256;
        int r = l >> 6, d = l & 63;
        Qs[r][d] = Qb[(size_t)(q0 + r) * HID + d];
        Ks[r][d] = Kb[(size_t)(k0 + r) * HID + d];
    }
    __syncthreads();
    float acc[4][4] = {};
    #pragma unroll 8
    for (int d = 0; d < 64; d++) {
        float a[4], bb[4];
        #pragma unroll
        for (int i = 0; i < 4; i++) a[i]  = Qs[ty * 4 + i][d];
        #pragma unroll
        for (int j = 0; j < 4; j++) bb[j] = Ks[tx * 4 + j][d];
        #pragma unroll
        for (int i = 0; i < 4; i++)
            #pragma unroll
            for (int j = 0; j < 4; j++)
                acc[i][j] = fmaf(a[i], bb[j], acc[i][j]);
    }
    float* Sb = S + (size_t)bh * LQ * LK;
    #pragma unroll
    for (int i = 0; i < 4; i++)
        #pragma unroll
        for (int j = 0; j < 4; j++)
            Sb[(size_t)(q0 + ty * 4 + i) * LK + k0 + tx * 4 + j] = acc[i][j] * 0.125f;
}

__global__ void attout_kernel(const float* __restrict__ S, float* __restrict__ O)
{
    int bq = blockIdx.x;
    int b = bq >> 9, q = bq & 511;
    int tid = threadIdx.x;
    #pragma unroll
    for (int i = 0; i < 4; i++) {
        int kc = tid + i * 256;
        float s = 0.0f;
        #pragma unroll
        for (int h = 0; h < NH; h++) {
            float x = S[(((size_t)(b * NH + h) * LQ) + q) * LK + kc];
            s += fmaxf(x, 0.0f);
        }
        O[(size_t)bq * LK + kc] = s * (1.0f / 16.0f);
    }
}

__global__ void softmax1024(float* __restrict__ P)
{
    __shared__ float red[256];
    size_t base = (size_t)blockIdx.x * 1024;
    int tid = threadIdx.x;
    float v[4];
    #pragma unroll
    for (int i = 0; i < 4; i++) v[i] = P[base + tid + i * 256];
    float m = fmaxf(fmaxf(v[0], v[1]), fmaxf(v[2], v[3]));
    red[tid] = m; __syncthreads();
    for (int o = 128; o > 0; o >>= 1) { if (tid < o) red[tid] = fmaxf(red[tid], red[tid + o]); __syncthreads(); }
    m = red[0]; __syncthreads();
    float s = 0.0f;
    #pragma unroll
    for (int i = 0; i < 4; i++) { v[i] = expf(v[i] - m); s += v[i]; }
    red[tid] = s; __syncthreads();
    for (int o = 128; o > 0; o >>= 1) { if (tid < o) red[tid] += red[tid + o]; __syncthreads(); }
    float inv = 1.0f / red[0];
    #pragma unroll
    for (int i = 0; i < 4; i++) P[base + tid + i * 256] = v[i] * inv;
}

__global__ void gemm_attv(const float* __restrict__ att, const float* __restrict__ V,
                          float* __restrict__ out)
{
    __shared__ float As[16][68];
    __shared__ float Bs[16][68];
    int bh = blockIdx.z, b = bh >> 4, h = bh & 15;
    int q0 = blockIdx.y * 64;
    const float* Ab = att + (size_t)bh * LQ * LK;
    const float* Bb = V + (size_t)b * LK * HID + h * 64;
    float* Cb = out + (size_t)b * LQ * HID + h * 64;
    int tid = threadIdx.x, tx = tid & 15, ty = tid >> 4;
    float acc[4][4] = {};
    for (int k0 = 0; k0 < LK; k0 += 16) {
        #pragma unroll
        for (int i = 0; i < 4; i++) {
            int l = tid + i * 256;
            int m = l >> 4, kk = l & 15;
            As[kk][m] = Ab[(size_t)(q0 + m) * LK + k0 + kk];
        }
        #pragma unroll
        for (int i = 0; i < 4; i++) {
            int ll = tid + i * 256;
            int kk = ll >> 6, d = ll & 63;
            Bs[kk][d] = Bb[(size_t)(k0 + kk) * HID + d];
        }
        __syncthreads();
        #pragma unroll
        for (int kk = 0; kk < 16; kk++) {
            float a[4], bb[4];
            #pragma unroll
            for (int i = 0; i < 4; i++) a[i]  = As[kk][ty * 4 + i];
            #pragma unroll
            for (int j = 0; j < 4; j++) bb[j] = Bs[kk][tx * 4 + j];
            #pragma unroll
            for (int i = 0; i < 4; i++)
                #pragma unroll
                for (int j = 0; j < 4; j++)
                    acc[i][j] = fmaf(a[i], bb[j], acc[i][j]);
        }
        __syncthreads();
    }
    #pragma unroll
    for (int i = 0; i < 4; i++)
        #pragma unroll
        for (int j = 0; j < 4; j++)
            Cb[(size_t)(q0 + ty * 4 + i) * HID + tx * 4 + j] = acc[i][j];
}

__global__ void xreduce_kernel(const float* __restrict__ q0p, const float* __restrict__ s,
                               float* __restrict__ xraw)
{
    int b = blockIdx.y;
    int c = blockIdx.x * 256 + threadIdx.x;
    const float* A  = q0p + (size_t)b * LQ * HID;
    const float* Bp = s   + (size_t)b * LQ * HID;
    float acc = 0.0f;
    for (int v = 0; v < LQ; v++)
        acc = fmaf(A[(size_t)v * HID + c], Bp[(size_t)v * HID + c], acc);
    xraw[b * HID + c] = acc;
}

__global__ void ln1024(const float* __restrict__ X, const float* __restrict__ R,
                       const float* __restrict__ ga, const float* __restrict__ be,
                       float* __restrict__ Y)
{
    __shared__ float red[256];
    int row = blockIdx.x, tid = threadIdx.x;
    size_t base = (size_t)row * 1024;
    float v[4];
    #pragma unroll
    for (int i = 0; i < 4; i++) {
        int c = tid + i * 256;
        v[i] = X[base + c];
        if (R) v[i] += R[base + c];
    }
    float s = v[0] + v[1] + v[2] + v[3];
    red[tid] = s; __syncthreads();
    for (int o = 128; o > 0; o >>= 1) { if (tid < o) red[tid] += red[tid + o]; __syncthreads(); }
    float mean = red[0] * (1.0f / 1024.0f);
    __syncthreads();
    float ss = 0.0f;
    #pragma unroll
    for (int i = 0; i < 4; i++) { float d = v[i] - mean; ss = fmaf(d, d, ss); }
    red[tid] = ss; __syncthreads();
    for (int o = 128; o > 0; o >>= 1) { if (tid < o) red[tid] += red[tid + o]; __syncthreads(); }
    float var = red[0] * (1.0f / 1023.0f);
    float inv = 1.0f / (sqrtf(var) + 1e-6f);
    #pragma unroll
    for (int i = 0; i < 4; i++) {
        int c = tid + i * 256;
        Y[base + c] = ga[c] * (v[i] - mean) * inv + be[c];
    }
}

// ======================= host side =========================================
#define GSYM(p, s) cudaGetSymbolAddress((void**)&p, s)

static void run_mm(const __nv_bfloat16* Ah, const __nv_bfloat16* Al,
                   const __nv_bfloat16* Bh, const __nv_bfloat16* Bl,
                   const float* bias, float* C, __nv_bfloat16* Ch, __nv_bfloat16* Cl,
                   int M, int N, int K, int relu)
{
    mm_bf16x3<<<dim3(N / 128, M / 128), 256, MM_SMEM>>>(
        Ah, Al, Bh, Bl, bias, C, Ch, Cl, M, N, K, relu);
}

extern "C" void kernel_launch(void* const* d_in, const int* in_sizes, int n_in,
                              void* d_out, int out_size)
{
    const float* q    = (const float*)d_in[0];
    const float* k    = (const float*)d_in[1];
    const float* Wq   = (const float*)d_in[2];
    const float* bq   = (const float*)d_in[3];
    const float* Wk   = (const float*)d_in[4];
    const float* bk   = (const float*)d_in[5];
    const float* Wv   = (const float*)d_in[6];
    const float* bv   = (const float*)d_in[7];
    const float* Wv0  = (const float*)d_in[8];
    const float* bv0  = (const float*)d_in[9];
    const float* Wq0  = (const float*)d_in[10];
    const float* bq0  = (const float*)d_in[11];
    const float* nq_a = (const float*)d_in[12];
    const float* nq_b = (const float*)d_in[13];
    const float* nx_a = (const float*)d_in[14];
    const float* nx_b = (const float*)d_in[15];
    const float* W1   = (const float*)d_in[16];
    const float* b1   = (const float*)d_in[17];
    const float* W2   = (const float*)d_in[18];
    const float* b2   = (const float*)d_in[19];
    const float* ns_a = (const float*)d_in[20];
    const float* ns_b = (const float*)d_in[21];

    float* out = (float*)d_out;
    float* out_x   = out;
    float* out_qq  = out + (size_t)B * HID;
    float* out_kp  = out_qq + (size_t)B * LQ * HID;
    float* out_att = out_kp + (size_t)B * LK * DIN;

    cudaFuncSetAttribute(mm_bf16x3, cudaFuncAttributeMaxDynamicSharedMemorySize, MM_SMEM);

    float *p_qh, *p_q0p, *p_kh, *p_v1, *p_v0, *p_sc, *p_ar, *p_s, *p_at, *p_f2, *p_xr;
    GSYM(p_qh, g_qh);  GSYM(p_q0p, g_q0p); GSYM(p_kh, g_kh); GSYM(p_v1, g_v1);
    GSYM(p_v0, g_v0);  GSYM(p_sc, g_scores); GSYM(p_ar, g_atted_raw); GSYM(p_s, g_s);
    GSYM(p_at, g_atted); GSYM(p_f2, g_ff2); GSYM(p_xr, g_xraw);

    __nv_bfloat16 *qp_h,*qp_l,*q_h,*q_l,*kp_h,*kp_l,*at_h,*at_l,*f1_h,*f1_l;
    __nv_bfloat16 *WqT_h,*WqT_l,*WkT_h,*WkT_l,*WvT_h,*WvT_l,*Wv0T_h,*Wv0T_l,*Wq0T_h,*Wq0T_l;
    __nv_bfloat16 *W1T_h,*W1T_l,*W2T_h,*W2T_l;
    GSYM(qp_h, g_qp_h); GSYM(qp_l, g_qp_l); GSYM(q_h, g_q_h); GSYM(q_l, g_q_l);
    GSYM(kp_h, g_kp_h); GSYM(kp_l, g_kp_l); GSYM(at_h, g_at_h); GSYM(at_l, g_at_l);
    GSYM(f1_h, g_f1_h); GSYM(f1_l, g_f1_l);
    GSYM(WqT_h, g_WqT_h); GSYM(WqT_l, g_WqT_l); GSYM(WkT_h, g_WkT_h); GSYM(WkT_l, g_WkT_l);
    GSYM(WvT_h, g_WvT_h); GSYM(WvT_l, g_WvT_l); GSYM(Wv0T_h, g_Wv0T_h); GSYM(Wv0T_l, g_Wv0T_l);
    GSYM(Wq0T_h, g_Wq0T_h); GSYM(Wq0T_l, g_Wq0T_l);
    GSYM(W1T_h, g_W1T_h); GSYM(W1T_l, g_W1T_l); GSYM(W2T_h, g_W2T_h); GSYM(W2T_l, g_W2T_l);

    // 1) positional encodings (+ bf16 splits); kp fp32 is an output
    {
        int tq = B * LQ * DIN, tk = B * LK * DIN;
        addpe_split<<<(tq + 255) / 256, 256>>>(q, nullptr, qp_h, qp_l, tq, LQ);
        addpe_split<<<(tk + 255) / 256, 256>>>(k, out_kp, kp_h, kp_l, tk, LK);
        split_kernel<<<(tq + 255) / 256, 256>>>(q, q_h, q_l, tq);
    }

    // 2) weight transposes + splits
    {
        dim3 t(32, 8);
        transpose_split<<<dim3(HID/32, DIN/32), t>>>(Wq,  WqT_h,  WqT_l,  DIN, HID);
        transpose_split<<<dim3(HID/32, DIN/32), t>>>(Wk,  WkT_h,  WkT_l,  DIN, HID);
        transpose_split<<<dim3(HID/32, DIN/32), t>>>(Wv,  WvT_h,  WvT_l,  DIN, HID);
        transpose_split<<<dim3(HID/32, DIN/32), t>>>(Wv0, Wv0T_h, Wv0T_l, DIN, HID);
        transpose_split<<<dim3(HID/32, DIN/32), t>>>(Wq0, Wq0T_h, Wq0T_l, DIN, HID);
        transpose_split<<<dim3(MID/32, HID/32), t>>>(W1,  W1T_h,  W1T_l,  HID, MID);
        transpose_split<<<dim3(HID/32, MID/32), t>>>(W2,  W2T_h,  W2T_l,  MID, HID);
    }

    // 3) projection GEMMs (HMMA bf16x3)
    run_mm(qp_h, qp_l, WqT_h,  WqT_l,  bq,  p_qh,  nullptr, nullptr, B*LQ, HID, DIN, 0);
    run_mm(q_h,  q_l,  Wq0T_h, Wq0T_l, bq0, p_q0p, nullptr, nullptr, B*LQ, HID, DIN, 0);
    run_mm(kp_h, kp_l, WkT_h,  WkT_l,  bk,  p_kh,  nullptr, nullptr, B*LK, HID, DIN, 0);
    run_mm(kp_h, kp_l, WvT_h,  WvT_l,  bv,  p_v1,  nullptr, nullptr, B*LK, HID, DIN, 0);
    run_mm(kp_h, kp_l, Wv0T_h, Wv0T_l, bv0, p_v0,  nullptr, nullptr, B*LK, HID, DIN, 0);

    // 4) attention (SIMT)
    gemm_scores<<<dim3(LK / 64, LQ / 64, B * NH), 256>>>(p_qh, p_kh, p_sc);
    attout_kernel<<<B * LQ, 256>>>(p_sc, out_att);
    softmax1024<<<B * NH * LQ, 256>>>(p_sc);
    gemm_attv<<<dim3(1, LQ / 64, B * NH), 256>>>(p_sc, p_v1, p_ar);
    gemm_attv<<<dim3(1, LQ / 64, B * NH), 256>>>(p_sc, p_v0, p_s);

    // 5) atted = LN(q0p + atted_raw), split for FFN
    ln1024<<<B * LQ, 256>>>(p_ar, p_q0p, nq_a, nq_b, p_at);
    split_kernel<<<(B*LQ*HID + 255) / 256, 256>>>(p_at, at_h, at_l, B*LQ*HID);

    // 6) bilinear branch -> x
    xreduce_kernel<<<dim3(HID / 256, B), 256>>>(p_q0p, p_s, p_xr);
    ln1024<<<B, 256>>>(p_xr, (const float*)nullptr, nx_a, nx_b, out_x);

    // 7) FFN (HMMA) + residual LN -> qq
    run_mm(at_h, at_l, W1T_h, W1T_l, b1, nullptr, f1_h, f1_l, B*LQ, MID, HID, 1);
    run_mm(f1_h, f1_l, W2T_h, W2T_l, b2, p_f2, nullptr, nullptr, B*LQ, HID, MID, 0);
    ln1024<<<B * LQ, 256>>>(p_f2, p_at, ns_a, ns_b, out_qq);
}